// round 14
// baseline (speedup 1.0000x reference)
#include <cuda_runtime.h>
#include <cuda_fp16.h>
#include <cstdint>

#define ODIM 1024
#define XSZ  4194304
#define WSZ  1048576
#define KOFF XSZ
#define VOFF (2*XSZ)
#define PPITCH 80            // proj smem pitch: 32 fp16 + 16B pad
#define APITCH 144           // attn smem pitch: 64 fp16 + 16B pad (pad holds vm col @128)
#define PJ_STG 30720         // A 256*80 + B 128*80
#define PJ_SMEM 92160        // 3 stages
#define AT_STG 36864         // K 128*144 + V 128*144
#define AT_SMEM 73728        // 2 stages

__device__ __align__(16) __half g_x[3*XSZ];   // fp16 q,k,v inputs
__device__ __align__(16) __half g_w[3*WSZ];   // fp16 weights
__device__ __align__(16) __half g_p[3*XSZ];   // fp16 projections qw,kw,vw (raw)
__device__ __align__(16) __half g_pv[XSZ];    // v-projection premasked by v_mask

// ---------------- helpers ----------------
__device__ __forceinline__ uint32_t smem_u32(const void* p) {
    uint32_t a;
    asm("{ .reg .u64 t; cvta.to.shared.u64 t, %1; cvt.u32.u64 %0, t; }" : "=r"(a) : "l"(p));
    return a;
}
__device__ __forceinline__ uint32_t packh2(float e0, float e1) {
    __half2 h = __floats2half2_rn(e0, e1);
    return *reinterpret_cast<uint32_t*>(&h);
}
__device__ __forceinline__ float ex2a(float x) {   // exp(s/8) == ex2(s*0.125*log2e)
    float r;
    asm("ex2.approx.f32 %0, %1;" : "=f"(r) : "f"(x));
    return r;
}
__device__ __forceinline__ void ldsm4(uint32_t* r, uint32_t a) {
    asm volatile("ldmatrix.sync.aligned.m8n8.x4.shared.b16 {%0,%1,%2,%3}, [%4];"
                 : "=r"(r[0]), "=r"(r[1]), "=r"(r[2]), "=r"(r[3]) : "r"(a));
}
__device__ __forceinline__ void ldsm4t(uint32_t* r, uint32_t a) {
    asm volatile("ldmatrix.sync.aligned.m8n8.x4.trans.shared.b16 {%0,%1,%2,%3}, [%4];"
                 : "=r"(r[0]), "=r"(r[1]), "=r"(r[2]), "=r"(r[3]) : "r"(a));
}
__device__ __forceinline__ void ldsm2t(uint32_t* r, uint32_t a) {
    asm volatile("ldmatrix.sync.aligned.m8n8.x2.trans.shared.b16 {%0,%1}, [%2];"
                 : "=r"(r[0]), "=r"(r[1]) : "r"(a));
}
__device__ __forceinline__ void mma_f16(float* d, const uint32_t* a, uint32_t b0, uint32_t b1) {
    asm volatile("mma.sync.aligned.m16n8k16.row.col.f32.f16.f16.f32 "
                 "{%0,%1,%2,%3}, {%4,%5,%6,%7}, {%8,%9}, {%0,%1,%2,%3};"
                 : "+f"(d[0]), "+f"(d[1]), "+f"(d[2]), "+f"(d[3])
                 : "r"(a[0]), "r"(a[1]), "r"(a[2]), "r"(a[3]), "r"(b0), "r"(b1));
}
#define CPA16(dst, src) asm volatile("cp.async.cg.shared.global [%0], [%1], 16;" :: "r"(dst), "l"(src) : "memory")
#define CPC()   asm volatile("cp.async.commit_group;" ::: "memory")
#define CPW(n)  asm volatile("cp.async.wait_group %0;" :: "n"(n) : "memory")

// ---------------- convert fp32 -> fp16 (3 tensors per launch) ----------------
__global__ void conv3(const float* __restrict__ s0, const float* __restrict__ s1,
                      const float* __restrict__ s2, __half* __restrict__ h, int n4each) {
    int i = blockIdx.x * blockDim.x + threadIdx.x;
    int a = i / n4each;
    if (a > 2) return;
    int j = i - a * n4each;
    const float* s = (a == 0) ? s0 : (a == 1) ? s1 : s2;
    float4 v = ((const float4*)s)[j];
    uint2 hh;
    hh.x = packh2(v.x, v.y);
    hh.y = packh2(v.z, v.w);
    ((uint2*)h)[(size_t)a * n4each + j] = hh;
}

// ---------------- projection: tile 256x128, warp 64x64, BK=32, 3-stage ----------------
__global__ __launch_bounds__(256, 1) void proj_mma(
    const __half* __restrict__ X_, const __half* __restrict__ W_,
    __half* __restrict__ P_, __half* __restrict__ PVm_,
    const float* __restrict__ vmask)
{
    extern __shared__ __align__(16) char sm[];
    const uint32_t sb = smem_u32(sm);
    const int z = blockIdx.z;
    const __half* A_ = X_ + (size_t)z * XSZ;
    const __half* B_ = W_ + (size_t)z * WSZ;
    __half* C_ = P_ + (size_t)z * XSZ;
    const int tid = threadIdx.x, wr = tid >> 5, lane = tid & 31;
    const int n0 = blockIdx.x * 128, m0 = blockIdx.y * 256;
    const int g = lane >> 2, t = lane & 3;
    const int wm = wr >> 1, wn = wr & 1;   // warp: rows wm*64, cols wn*64
    const uint32_t rB  = ((lane >> 4) & 1) * 8 + (lane & 7);
    const uint32_t cBo = ((lane >> 3) & 1) * 16;
    float acc[4][8][4] = {};

    auto issue = [&](int kt) {
        if (kt < 32) {
            const uint32_t base = sb + (uint32_t)(kt % 3) * PJ_STG;
            #pragma unroll
            for (int i = 0; i < 4; i++) {                    // A: 256 rows x 4 chunks
                int idx = tid + 256 * i;
                int r = idx >> 2, gc = idx & 3;
                CPA16(base + r * PPITCH + gc * 16,
                      A_ + (size_t)(m0 + r) * ODIM + kt * 32 + gc * 8);
            }
            #pragma unroll
            for (int i = 0; i < 2; i++) {                    // B: 128 rows x 4 chunks
                int idx = tid + 256 * i;
                int r = idx >> 2, gc = idx & 3;
                CPA16(base + 20480 + r * PPITCH + gc * 16,
                      B_ + (size_t)(n0 + r) * ODIM + kt * 32 + gc * 8);
            }
        }
        CPC();
    };

    issue(0); issue(1);
    for (int kt = 0; kt < 32; kt++) {
        CPW(1);
        __syncthreads();
        issue(kt + 2);
        const uint32_t base = sb + (uint32_t)(kt % 3) * PJ_STG;
        #pragma unroll
        for (int kc = 0; kc < 2; kc++) {
            uint32_t ah[4][4];
            #pragma unroll
            for (int mi = 0; mi < 4; mi++)
                ldsm4(ah[mi], base + (wm * 64 + mi * 16 + (lane & 15)) * PPITCH
                              + (lane >> 4) * 16 + kc * 32);
            #pragma unroll
            for (int bj = 0; bj < 4; bj++) {
                uint32_t bh[4];
                ldsm4(bh, base + 20480 + (wn * 64 + bj * 16 + rB) * PPITCH + cBo + kc * 32);
                #pragma unroll
                for (int mi = 0; mi < 4; mi++) {
                    mma_f16(acc[mi][2*bj],   ah[mi], bh[0], bh[1]);
                    mma_f16(acc[mi][2*bj+1], ah[mi], bh[2], bh[3]);
                }
            }
        }
    }
    #pragma unroll
    for (int mi = 0; mi < 4; mi++) {
        const int r0 = m0 + wm * 64 + mi * 16 + g, r1 = r0 + 8;
        float s0 = 1.f, s1 = 1.f;
        if (z == 2) { s0 = vmask[r0]; s1 = vmask[r1]; }
        #pragma unroll
        for (int nj = 0; nj < 8; nj++) {
            int col = n0 + wn * 64 + nj * 8 + 2 * t;
            float c0 = acc[mi][nj][0], c1 = acc[mi][nj][1];
            float c2 = acc[mi][nj][2], c3 = acc[mi][nj][3];
            *(uint32_t*)(C_ + (size_t)r0 * ODIM + col) = packh2(c0, c1);
            *(uint32_t*)(C_ + (size_t)r1 * ODIM + col) = packh2(c2, c3);
            if (z == 2) {
                *(uint32_t*)(PVm_ + (size_t)r0 * ODIM + col) = packh2(c0 * s0, c1 * s0);
                *(uint32_t*)(PVm_ + (size_t)r1 * ODIM + col) = packh2(c2 * s1, c3 * s1);
            }
        }
    }
}

// ---------------- attention: 128 q-rows/CTA, 4 warps x 32 rows, 128-key tiles, 2-stage ----------------
__global__ __launch_bounds__(128, 3) void attn_mma(
    const float* __restrict__ v_mask, const float* __restrict__ q_mask,
    float* __restrict__ out, const __half* __restrict__ P_,
    const __half* __restrict__ PVm_)
{
    extern __shared__ __align__(16) char sm[];
    const uint32_t sb = smem_u32(sm);
    const int tid = threadIdx.x, wr = tid >> 5, lane = tid & 31;
    const int qt = blockIdx.x, h = blockIdx.y, b = blockIdx.z;
    const int q0 = qt * 128;
    const int g = lane >> 2, t = lane & 3;
    const uint32_t rB  = ((lane >> 4) & 1) * 8 + (lane & 7);
    const uint32_t cBo = ((lane >> 3) & 1) * 16;

    const __half* Q_b  = P_ + (size_t)(b * 2048 + q0) * ODIM + h * 64;
    const __half* K_b  = P_ + KOFF + (size_t)(b * 2048) * ODIM + h * 64;
    const __half* Vm_b = PVm_ + (size_t)(b * 2048) * ODIM + h * 64;
    const float* vm = v_mask + (size_t)b * 2048;

    // ---- stage full Q tile (128 rows) into stage-0 K area, grab fragments ----
    uint32_t qA[2][4][4];
    #pragma unroll
    for (int i = 0; i < 8; i++) {
        int idx = tid + 128 * i;              // 1024 = 128 rows x 8 chunks
        int r = idx >> 3, gc = idx & 7;
        *(uint4*)(sm + r * APITCH + gc * 16) =
            *(const uint4*)(Q_b + (size_t)r * ODIM + gc * 8);
    }
    __syncthreads();
    #pragma unroll
    for (int mi = 0; mi < 2; mi++)
        #pragma unroll
        for (int kc = 0; kc < 4; kc++)
            ldsm4(qA[mi][kc], sb + (wr * 32 + mi * 16 + (lane & 15)) * APITCH
                              + (lane >> 4) * 16 + kc * 32);
    __syncthreads();

    float oacc[2][8][4] = {};
    float lacc[2][4] = {};
    const int rmin = q0 + wr * 32, rmax = rmin + 31;

    auto issue = [&](int kt2) {
        if (kt2 < 16) {
            const int st = kt2 & 1;
            const int k0 = kt2 * 128;
            const uint32_t bs = sb + (uint32_t)st * AT_STG;
            #pragma unroll
            for (int i = 0; i < 16; i++) {    // 2048 = 2 arrays x 128 rows x 8 chunks
                int idx = tid + 128 * i;
                int arr = idx >> 10, r = (idx >> 3) & 127, gc = idx & 7;
                CPA16(bs + arr * 18432 + r * APITCH + gc * 16,
                      (arr ? Vm_b : K_b) + (size_t)(k0 + r) * ODIM + gc * 8);
            }
            // vm column (fp16) into V row padding @byte 128
            *(__half*)(sm + st * AT_STG + 18432 + tid * APITCH + 128) =
                __float2half(vm[k0 + tid]);
        }
        CPC();
    };

    const int start = qt;
    issue(start);
    for (int kt2 = start; kt2 < 16; kt2++) {
        CPW(0);
        __syncthreads();
        issue(kt2 + 1);
        const int st = kt2 & 1;
        const int k0 = kt2 * 128;
        const uint32_t bKs = sb + (uint32_t)st * AT_STG;
        const uint32_t bVs = bKs + 18432;
        const bool bt = (kt2 == start);

        #pragma unroll
        for (int jp = 0; jp < 8; jp++) {
            if (bt && (k0 + jp * 16 + 15 <= rmin)) continue;   // fully causal-masked chunk
            float s8[2][8] = {};
            #pragma unroll
            for (int kc = 0; kc < 4; kc++) {
                uint32_t bh[4];
                ldsm4(bh, bKs + (jp * 16 + rB) * APITCH + cBo + kc * 32);
                #pragma unroll
                for (int mi = 0; mi < 2; mi++) {
                    mma_f16(s8[mi] + 0, qA[mi][kc], bh[0], bh[1]);
                    mma_f16(s8[mi] + 4, qA[mi][kc], bh[2], bh[3]);
                }
            }
            const bool ew = bt && (k0 + jp * 16 <= rmax);
            uint32_t pa[2][4];
            #pragma unroll
            for (int mi = 0; mi < 2; mi++) {
                const int qrow0 = rmin + mi * 16 + g;
                float p[8];
                if (ew) {
                    const int cb = jp * 16 + 2 * t;
                    #pragma unroll
                    for (int e = 0; e < 8; e++) {
                        int tile = e >> 2, c = e & 3;
                        int kg = k0 + cb + tile * 8 + (c & 1);
                        int qr = (c >= 2) ? qrow0 + 8 : qrow0;
                        p[e] = (kg <= qr) ? 0.f : ex2a(s8[mi][e] * 0.18033688f);
                    }
                } else {
                    #pragma unroll
                    for (int e = 0; e < 8; e++) p[e] = ex2a(s8[mi][e] * 0.18033688f);
                }
                pa[mi][0] = packh2(p[0], p[1]);  pa[mi][1] = packh2(p[2], p[3]);
                pa[mi][2] = packh2(p[4], p[5]);  pa[mi][3] = packh2(p[6], p[7]);
            }
            #pragma unroll
            for (int j2 = 0; j2 < 4; j2++) {
                uint32_t vh[4];
                ldsm4t(vh, bVs + (jp * 16 + (lane & 15)) * APITCH + (j2 * 2 + (lane >> 4)) * 16);
                #pragma unroll
                for (int mi = 0; mi < 2; mi++) {
                    mma_f16(oacc[mi][2*j2],   pa[mi], vh[0], vh[1]);
                    mma_f16(oacc[mi][2*j2+1], pa[mi], vh[2], vh[3]);
                }
            }
            uint32_t u[2];
            ldsm2t(u, bVs + (jp * 16 + (lane & 15)) * APITCH + 128);
            mma_f16(lacc[0], pa[0], u[0], u[1]);
            mma_f16(lacc[1], pa[1], u[0], u[1]);
        }
    }

    // ---- epilogue: lr lives in accumulator col 0 (lanes t==0); broadcast within 4-lane group ----
    #pragma unroll
    for (int mi = 0; mi < 2; mi++) {
        const float lrA = __shfl_sync(0xffffffffu, lacc[mi][0], lane & 28);
        const float lrB = __shfl_sync(0xffffffffu, lacc[mi][2], lane & 28);
        const int r0 = q0 + wr * 32 + mi * 16 + g, r1 = r0 + 8;
        const float qm0 = q_mask[(size_t)b * 2048 + r0];
        const float qm1 = q_mask[(size_t)b * 2048 + r1];
        const float inv0 = (lrA > 0.f) ? qm0 / lrA : 0.f;
        const float inv1 = (lrB > 0.f) ? qm1 / lrB : 0.f;
        float* o0 = out + (size_t)(b * 2048 + r0) * ODIM + h * 64;
        float* o1 = out + (size_t)(b * 2048 + r1) * ODIM + h * 64;
        #pragma unroll
        for (int j = 0; j < 8; j++) {
            *(float2*)(o0 + j * 8 + 2 * t) =
                make_float2(oacc[mi][j][0] * inv0, oacc[mi][j][1] * inv0);
            *(float2*)(o1 + j * 8 + 2 * t) =
                make_float2(oacc[mi][j][2] * inv1, oacc[mi][j][3] * inv1);
        }
    }
}

// ---------------- degenerate rows (q >= last valid key): exact tie-average ----------------
__global__ __launch_bounds__(512) void fallback_k(
    const float* __restrict__ v_mask, const float* __restrict__ q_mask,
    float* __restrict__ out, const __half* __restrict__ Vw)
{
    __shared__ int smax[512], scnt[512];
    __shared__ float spart[512];
    const int h = blockIdx.x, b = blockIdx.y, tid = threadIdx.x;
    const float* vm = v_mask + (size_t)b * 2048;

    int km = -1, c = 0;
    for (int k2 = tid; k2 < 2048; k2 += 512)
        if (vm[k2] != 0.f) { if (k2 > km) km = k2; c++; }
    smax[tid] = km; scnt[tid] = c;
    __syncthreads();
    for (int s = 256; s > 0; s >>= 1) {
        if (tid < s) {
            if (smax[tid + s] > smax[tid]) smax[tid] = smax[tid + s];
            scnt[tid] += scnt[tid + s];
        }
        __syncthreads();
    }
    const int kmax = (smax[0] < 0) ? 0 : smax[0];
    const int cnt = scnt[0];

    const int d = tid & 63, sl = tid >> 6;
    const __half* vh = Vw + (size_t)(b * 2048) * ODIM + h * 64 + d;
    float part = 0.f;
    for (int k2 = sl * 256; k2 < sl * 256 + 256; k2++)
        if (vm[k2] != 0.f) part += __half2float(vh[(size_t)k2 * ODIM]);
    spart[tid] = part;
    __syncthreads();

    if (tid < 64) {
        float tm = 0.f;
        #pragma unroll
        for (int s = 0; s < 8; s++) tm += spart[s * 64 + d];
        float suf = 0.f;
        for (int k2 = 2047; k2 >= kmax; k2--) {
            const float qm = q_mask[(size_t)b * 2048 + k2];
            const int den = cnt + (2047 - k2);
            out[((size_t)(b * 2048 + k2)) * ODIM + h * 64 + d] =
                (den > 0) ? qm * (tm + suf) / (float)den : 0.f;
            suf += __half2float(vh[(size_t)k2 * ODIM]);
        }
    }
}

// ---------------- launch ----------------
extern "C" void kernel_launch(void* const* d_in, const int* in_sizes, int n_in,
                              void* d_out, int out_size)
{
    const float* q     = (const float*)d_in[0];
    const float* k     = (const float*)d_in[1];
    const float* v     = (const float*)d_in[2];
    const float* vmask = (const float*)d_in[3];
    const float* qmask = (const float*)d_in[4];
    const float* Wq    = (const float*)d_in[5];
    const float* Wk    = (const float*)d_in[6];
    const float* Wv    = (const float*)d_in[7];
    float* out = (float*)d_out;

    __half *x16, *w16, *p16, *pv16;
    cudaGetSymbolAddress((void**)&x16, g_x);
    cudaGetSymbolAddress((void**)&w16, g_w);
    cudaGetSymbolAddress((void**)&p16, g_p);
    cudaGetSymbolAddress((void**)&pv16, g_pv);

    cudaFuncSetAttribute(proj_mma, cudaFuncAttributeMaxDynamicSharedMemorySize, PJ_SMEM);
    cudaFuncSetAttribute(attn_mma, cudaFuncAttributeMaxDynamicSharedMemorySize, AT_SMEM);

    conv3<<<12288, 256>>>(q, k, v, x16, XSZ / 4);
    conv3<<<3072, 256>>>(Wq, Wk, Wv, w16, WSZ / 4);
    proj_mma<<<dim3(8, 16, 3), 256, PJ_SMEM>>>(x16, w16, p16, pv16, vmask);
    attn_mma<<<dim3(16, 16, 2), 128, AT_SMEM>>>(vmask, qmask, out, p16, pv16);
    fallback_k<<<dim3(16, 2), 512>>>(vmask, qmask, out, p16 + 2*XSZ);
}